// round 6
// baseline (speedup 1.0000x reference)
#include <cuda_runtime.h>

// Problem constants (fixed by reference setup_inputs)
#define BB 128
#define SS 256
#define HH 768
#define KK 64
#define NROWS (BB * SS)     // 32768
#define V4_PER_ROW (HH / 4) // 192

// One block per (b,s) row, 192 threads (6 warps), one float4 per thread.
//
// Membership is fully WARP-LOCAL: each warp checks all three 64-entry lists
// itself (2 entries per lane per list via one int2 load each -> 3x LDG.64,
// all L2-hit broadcast), then 3 ballots. No __syncthreads, no shared memory,
// no cross-warp dependency: each warp's stores release as soon as its own
// loads return. The streaming input LDG is issued first so the index loads
// and ballots hide under its ~600-cycle HBM latency.
//
// Validity: indices lie in [0, S) and target = s-1 <= S-2, so idx == S-1
// never matches -- identical to the reference's (idx + 1 < S) check.
__global__ __launch_bounds__(V4_PER_ROW) void fused_kernel(
    const float4* __restrict__ in,
    const int*    __restrict__ depend,
    const int*    __restrict__ depended,
    const int*    __restrict__ noconn,
    const float*  __restrict__ dep_w,
    const float*  __restrict__ dpd_w,
    float4*       __restrict__ out)
{
    const int row = blockIdx.x;
    const int t   = threadIdx.x;

    // 1) issue streaming load immediately (latency overlapped below)
    const long idx = (long)row * V4_PER_ROW + t;
    const float4 v = in[idx];

    // 2) warp-local membership (L2-resident index arrays)
    const int b      = row >> 8;        // row / SS
    const int s      = row & (SS - 1);  // row % SS
    const int target = s - 1;           // s=0 -> -1, never matches (idx >= 0)
    const int lane   = t & 31;

    const int2 d2 = __ldg(&((const int2*)(depend   + b * KK))[lane]);
    const int2 e2 = __ldg(&((const int2*)(depended + b * KK))[lane]);
    const int2 n2 = __ldg(&((const int2*)(noconn   + b * KK))[lane]);

    const bool dep = __ballot_sync(0xffffffffu, (d2.x == target) | (d2.y == target)) != 0;
    const bool dpd = __ballot_sync(0xffffffffu, (e2.x == target) | (e2.y == target)) != 0;
    const bool noc = __ballot_sync(0xffffffffu, (n2.x == target) | (n2.y == target)) != 0;
    const bool p0  = (s == 0);

    const float m0 = (p0 || dep) ? 1.0f : 0.0f;
    const float m1 = (p0 || dpd) ? 1.0f : 0.0f;
    float m2 = dep ? __ldg(&dep_w[b]) : 0.0f;
    if (dpd) m2 = __ldg(&dpd_w[b]);
    if (noc) m2 = 0.0f;
    if (p0)  m2 = 1.0f;

    // 3) multiply + 3 coalesced streaming stores
    float4 a, bb, c;
    a.x  = v.x * m0; a.y  = v.y * m0; a.z  = v.z * m0; a.w  = v.w * m0;
    bb.x = v.x * m1; bb.y = v.y * m1; bb.z = v.z * m1; bb.w = v.w * m1;
    c.x  = v.x * m2; c.y  = v.y * m2; c.z  = v.z * m2; c.w  = v.w * m2;

    const long N4 = (long)NROWS * V4_PER_ROW;
    out[idx]          = a;
    out[N4 + idx]     = bb;
    out[2 * N4 + idx] = c;
}

extern "C" void kernel_launch(void* const* d_in, const int* in_sizes, int n_in,
                              void* d_out, int out_size) {
    const float* bert     = (const float*)d_in[0];
    const int*   depend   = (const int*)d_in[1];
    const int*   depended = (const int*)d_in[2];
    const int*   noconn   = (const int*)d_in[3];
    const float* dep_w    = (const float*)d_in[4];
    const float* dpd_w    = (const float*)d_in[5];
    float*       out      = (float*)d_out;

    fused_kernel<<<NROWS, V4_PER_ROW>>>((const float4*)bert, depend, depended,
                                        noconn, dep_w, dpd_w, (float4*)out);
}

// round 7
// speedup vs baseline: 1.0219x; 1.0219x over previous
#include <cuda_runtime.h>

// Problem constants (fixed by reference setup_inputs)
#define BB 128
#define SS 256
#define HH 768
#define KK 64
#define NROWS (BB * SS)     // 32768
#define V4_PER_ROW (HH / 4) // 192

// One block per (b,s) row, 192 threads (6 warps), one float4 per thread.
//
// Membership is done by WARP 0 ONLY: 3x int2 L2/L1-hit loads (2 entries per
// lane per list), 6 compares, 3 ballots; lane 0 folds in the weights and
// writes the three final multipliers to smem. One __syncthreads, then all
// threads read 3 broadcast LDS values. Warps 1-5 execute exactly the
// minimal streaming sequence: LDG -> bar -> 3 LDS -> 12 FMUL -> 3 STG;
// their barrier wait hides under their own input load's ~600-cycle DRAM
// latency (warp 0's L2 membership path is ~2.5x shorter).
//
// Validity: indices lie in [0, S) and target = s-1 <= S-2, so idx == S-1
// never matches -- identical to the reference's (idx + 1 < S) check.
__global__ __launch_bounds__(V4_PER_ROW) void fused_kernel(
    const float4* __restrict__ in,
    const int*    __restrict__ depend,
    const int*    __restrict__ depended,
    const int*    __restrict__ noconn,
    const float*  __restrict__ dep_w,
    const float*  __restrict__ dpd_w,
    float4*       __restrict__ out)
{
    const unsigned row = blockIdx.x;
    const unsigned t   = threadIdx.x;

    // 1) issue streaming load immediately (latency overlapped below)
    const unsigned idx = row * V4_PER_ROW + t;
    const float4 v = in[idx];

    __shared__ float sh_m[3];

    // 2) membership: warp 0 only
    if (t < 32) {
        const int b      = row >> 8;        // row / SS
        const int s      = row & (SS - 1);  // row % SS
        const int target = s - 1;           // s=0 -> -1, never matches

        // weights issued before the ballots (no dependent load afterward)
        const float w1 = __ldg(&dep_w[b]);
        const float w2 = __ldg(&dpd_w[b]);

        const int2 d2 = __ldg(&((const int2*)(depend   + b * KK))[t]);
        const int2 e2 = __ldg(&((const int2*)(depended + b * KK))[t]);
        const int2 n2 = __ldg(&((const int2*)(noconn   + b * KK))[t]);

        const bool dep = __ballot_sync(0xffffffffu,
                            (d2.x == target) | (d2.y == target)) != 0;
        const bool dpd = __ballot_sync(0xffffffffu,
                            (e2.x == target) | (e2.y == target)) != 0;
        const bool noc = __ballot_sync(0xffffffffu,
                            (n2.x == target) | (n2.y == target)) != 0;

        if (t == 0) {
            const bool p0 = (s == 0);
            sh_m[0] = (p0 || dep) ? 1.0f : 0.0f;
            sh_m[1] = (p0 || dpd) ? 1.0f : 0.0f;
            float m2 = dep ? w1 : 0.0f;
            if (dpd) m2 = w2;
            if (noc) m2 = 0.0f;
            if (p0)  m2 = 1.0f;
            sh_m[2] = m2;
        }
    }
    __syncthreads();

    const float m0 = sh_m[0];
    const float m1 = sh_m[1];
    const float m2 = sh_m[2];

    // 3) multiply + 3 coalesced streaming stores
    float4 a, bb, c;
    a.x  = v.x * m0; a.y  = v.y * m0; a.z  = v.z * m0; a.w  = v.w * m0;
    bb.x = v.x * m1; bb.y = v.y * m1; bb.z = v.z * m1; bb.w = v.w * m1;
    c.x  = v.x * m2; c.y  = v.y * m2; c.z  = v.z * m2; c.w  = v.w * m2;

    const unsigned N4 = NROWS * V4_PER_ROW;
    out[idx]           = a;
    out[N4 + idx]      = bb;
    out[2u * N4 + idx] = c;
}

extern "C" void kernel_launch(void* const* d_in, const int* in_sizes, int n_in,
                              void* d_out, int out_size) {
    const float* bert     = (const float*)d_in[0];
    const int*   depend   = (const int*)d_in[1];
    const int*   depended = (const int*)d_in[2];
    const int*   noconn   = (const int*)d_in[3];
    const float* dep_w    = (const float*)d_in[4];
    const float* dpd_w    = (const float*)d_in[5];
    float*       out      = (float*)d_out;

    fused_kernel<<<NROWS, V4_PER_ROW>>>((const float4*)bert, depend, depended,
                                        noconn, dep_w, dpd_w, (float4*)out);
}

// round 8
// speedup vs baseline: 1.1439x; 1.1194x over previous
#include <cuda_runtime.h>

// Problem constants (fixed by reference setup_inputs)
#define BB 128
#define SS 256
#define HH 768
#define KK 64
#define NROWS (BB * SS)     // 32768
#define V4_PER_ROW (HH / 4) // 192

// One block per (b,s) row, 192 threads (6 warps), one float4 per thread.
//
// Membership by warp 0 only (R7 structure): 3x int2 L2-hit loads, 3 ballots,
// lane 0 folds in weights and writes the three multipliers to smem; one
// __syncthreads; all threads read 3 broadcast LDS values.
//
// NEW: read-skip. A row is all-zero in all three outputs iff
// s != 0 && !dep && !dpd (m2 can only be nonzero via dep/dpd). That holds
// for ~60% of rows under the input distribution, so for those rows we skip
// the 3 KB input read entirely and store zeros (output buffer is poisoned,
// so zero rows MUST still be written). Block-uniform branch -> no divergence.
// Cuts total HBM traffic ~15% (403 -> ~342 MB).
//
// Validity: indices lie in [0, S) and target = s-1 <= S-2, so idx == S-1
// never matches -- identical to the reference's (idx + 1 < S) check.
__global__ __launch_bounds__(V4_PER_ROW) void fused_kernel(
    const float4* __restrict__ in,
    const int*    __restrict__ depend,
    const int*    __restrict__ depended,
    const int*    __restrict__ noconn,
    const float*  __restrict__ dep_w,
    const float*  __restrict__ dpd_w,
    float4*       __restrict__ out)
{
    const unsigned row = blockIdx.x;
    const unsigned t   = threadIdx.x;

    __shared__ float sh_m[3];
    __shared__ int   sh_skip;

    // membership: warp 0 only
    if (t < 32) {
        const int b      = row >> 8;        // row / SS
        const int s      = row & (SS - 1);  // row % SS
        const int target = s - 1;           // s=0 -> -1, never matches

        const float w1 = __ldg(&dep_w[b]);
        const float w2 = __ldg(&dpd_w[b]);

        const int2 d2 = __ldg(&((const int2*)(depend   + b * KK))[t]);
        const int2 e2 = __ldg(&((const int2*)(depended + b * KK))[t]);
        const int2 n2 = __ldg(&((const int2*)(noconn   + b * KK))[t]);

        const bool dep = __ballot_sync(0xffffffffu,
                            (d2.x == target) | (d2.y == target)) != 0;
        const bool dpd = __ballot_sync(0xffffffffu,
                            (e2.x == target) | (e2.y == target)) != 0;
        const bool noc = __ballot_sync(0xffffffffu,
                            (n2.x == target) | (n2.y == target)) != 0;

        if (t == 0) {
            const bool p0 = (s == 0);
            sh_m[0] = (p0 || dep) ? 1.0f : 0.0f;
            sh_m[1] = (p0 || dpd) ? 1.0f : 0.0f;
            float m2 = dep ? w1 : 0.0f;
            if (dpd) m2 = w2;
            if (noc) m2 = 0.0f;
            if (p0)  m2 = 1.0f;
            sh_m[2] = m2;
            sh_skip = (!p0 && !dep && !dpd) ? 1 : 0;
        }
    }
    __syncthreads();

    const unsigned idx = row * V4_PER_ROW + t;
    const unsigned N4  = NROWS * V4_PER_ROW;

    if (sh_skip) {
        // all three outputs zero for this row: no input read needed
        const float4 z = make_float4(0.0f, 0.0f, 0.0f, 0.0f);
        out[idx]           = z;
        out[N4 + idx]      = z;
        out[2u * N4 + idx] = z;
        return;
    }

    const float m0 = sh_m[0];
    const float m1 = sh_m[1];
    const float m2 = sh_m[2];

    const float4 v = in[idx];

    float4 a, bb, c;
    a.x  = v.x * m0; a.y  = v.y * m0; a.z  = v.z * m0; a.w  = v.w * m0;
    bb.x = v.x * m1; bb.y = v.y * m1; bb.z = v.z * m1; bb.w = v.w * m1;
    c.x  = v.x * m2; c.y  = v.y * m2; c.z  = v.z * m2; c.w  = v.w * m2;

    out[idx]           = a;
    out[N4 + idx]      = bb;
    out[2u * N4 + idx] = c;
}

extern "C" void kernel_launch(void* const* d_in, const int* in_sizes, int n_in,
                              void* d_out, int out_size) {
    const float* bert     = (const float*)d_in[0];
    const int*   depend   = (const int*)d_in[1];
    const int*   depended = (const int*)d_in[2];
    const int*   noconn   = (const int*)d_in[3];
    const float* dep_w    = (const float*)d_in[4];
    const float* dpd_w    = (const float*)d_in[5];
    float*       out      = (float*)d_out;

    fused_kernel<<<NROWS, V4_PER_ROW>>>((const float4*)bert, depend, depended,
                                        noconn, dep_w, dpd_w, (float4*)out);
}

// round 9
// speedup vs baseline: 1.1760x; 1.0281x over previous
#include <cuda_runtime.h>

// Problem constants (fixed by reference setup_inputs)
#define BB 128
#define SS 256
#define HH 768
#define KK 64
#define NROWS (BB * SS)     // 32768
#define V4_PER_ROW (HH / 4) // 192

// One block per (b,s) row, 192 threads (6 warps), one float4 per thread.
//
// R8 structure (committed): warp-0-only membership via 3x int2 L2-hit loads
// + 3 ballots; lane 0 folds weights into three multipliers in smem; one
// __syncthreads; broadcast LDS. Read-skip: rows with s!=0 && !dep && !dpd
// are all-zero in all three outputs (~60% of rows) -> store zeros, skip the
// 3 KB input read.
//
// R9 change (isolated A/B): streaming cache hints. Output is 302 MB of
// write-once data -> __stcs (evict-first) to cut L2 dirty-line dwell;
// input is read-once -> __ldcs. Nothing else changed vs R8.
//
// Validity: indices lie in [0, S) and target = s-1 <= S-2, so idx == S-1
// never matches -- identical to the reference's (idx + 1 < S) check.
__global__ __launch_bounds__(V4_PER_ROW) void fused_kernel(
    const float4* __restrict__ in,
    const int*    __restrict__ depend,
    const int*    __restrict__ depended,
    const int*    __restrict__ noconn,
    const float*  __restrict__ dep_w,
    const float*  __restrict__ dpd_w,
    float4*       __restrict__ out)
{
    const unsigned row = blockIdx.x;
    const unsigned t   = threadIdx.x;

    __shared__ float sh_m[3];
    __shared__ int   sh_skip;

    // membership: warp 0 only
    if (t < 32) {
        const int b      = row >> 8;        // row / SS
        const int s      = row & (SS - 1);  // row % SS
        const int target = s - 1;           // s=0 -> -1, never matches

        const float w1 = __ldg(&dep_w[b]);
        const float w2 = __ldg(&dpd_w[b]);

        const int2 d2 = __ldg(&((const int2*)(depend   + b * KK))[t]);
        const int2 e2 = __ldg(&((const int2*)(depended + b * KK))[t]);
        const int2 n2 = __ldg(&((const int2*)(noconn   + b * KK))[t]);

        const bool dep = __ballot_sync(0xffffffffu,
                            (d2.x == target) | (d2.y == target)) != 0;
        const bool dpd = __ballot_sync(0xffffffffu,
                            (e2.x == target) | (e2.y == target)) != 0;
        const bool noc = __ballot_sync(0xffffffffu,
                            (n2.x == target) | (n2.y == target)) != 0;

        if (t == 0) {
            const bool p0 = (s == 0);
            sh_m[0] = (p0 || dep) ? 1.0f : 0.0f;
            sh_m[1] = (p0 || dpd) ? 1.0f : 0.0f;
            float m2 = dep ? w1 : 0.0f;
            if (dpd) m2 = w2;
            if (noc) m2 = 0.0f;
            if (p0)  m2 = 1.0f;
            sh_m[2] = m2;
            sh_skip = (!p0 && !dep && !dpd) ? 1 : 0;
        }
    }
    __syncthreads();

    const unsigned idx = row * V4_PER_ROW + t;
    const unsigned N4  = NROWS * V4_PER_ROW;

    if (sh_skip) {
        // all three outputs zero for this row: no input read needed
        const float4 z = make_float4(0.0f, 0.0f, 0.0f, 0.0f);
        __stcs(&out[idx],           z);
        __stcs(&out[N4 + idx],      z);
        __stcs(&out[2u * N4 + idx], z);
        return;
    }

    const float m0 = sh_m[0];
    const float m1 = sh_m[1];
    const float m2 = sh_m[2];

    const float4 v = __ldcs(&in[idx]);   // read-once: evict-first

    float4 a, bb, c;
    a.x  = v.x * m0; a.y  = v.y * m0; a.z  = v.z * m0; a.w  = v.w * m0;
    bb.x = v.x * m1; bb.y = v.y * m1; bb.z = v.z * m1; bb.w = v.w * m1;
    c.x  = v.x * m2; c.y  = v.y * m2; c.z  = v.z * m2; c.w  = v.w * m2;

    __stcs(&out[idx],           a);      // write-once: evict-first
    __stcs(&out[N4 + idx],      bb);
    __stcs(&out[2u * N4 + idx], c);
}

extern "C" void kernel_launch(void* const* d_in, const int* in_sizes, int n_in,
                              void* d_out, int out_size) {
    const float* bert     = (const float*)d_in[0];
    const int*   depend   = (const int*)d_in[1];
    const int*   depended = (const int*)d_in[2];
    const int*   noconn   = (const int*)d_in[3];
    const float* dep_w    = (const float*)d_in[4];
    const float* dpd_w    = (const float*)d_in[5];
    float*       out      = (float*)d_out;

    fused_kernel<<<NROWS, V4_PER_ROW>>>((const float4*)bert, depend, depended,
                                        noconn, dep_w, dpd_w, (float4*)out);
}